// round 16
// baseline (speedup 1.0000x reference)
#include <cuda_runtime.h>
#include <cuda_fp16.h>
#include <math.h>
#include <stdint.h>

#define NROI 4096
#define DIM  1024
#define HID  512
#define NCLS 21
#define NBBX 84
#define NHEAD 105         // 84 + 21
#define NHPAD 128
#define NW   128
#define CCB  128

typedef unsigned long long ULL;

// ================= scratch (static device globals) ===========================
__device__ float  g_xn[NROI * DIM];
__device__ float  g_d[NROI];
__device__ float  g_t1[NROI * HID];
__device__ float  g_upart[4 * DIM * HID];
__device__ float  g_t2[NROI * HID];
__device__ unsigned g_adj[NROI * NW];
__device__ int    g_lab[2][NROI];
__device__ float  g_logits[NROI * NCLS];
__device__ int    g_diffs[33];
__device__ ULL    g_barc;
__device__ float  g_bc[NHPAD];
// fp16 operands: *h/*l = hi/lo split (A-side); single arrays = rounded (B-side)
__device__ __half g_pfh[NROI * DIM],  g_pfl[NROI * DIM];
__device__ __half g_xnh[NROI * DIM],  g_xnl[NROI * DIM];
__device__ __half g_xnT[DIM * NROI];
__device__ __half g_w1T[HID * DIM];
__device__ __half g_w2T[HID * HID];
__device__ __half g_tTh[HID * NROI],  g_tTl[HID * NROI];
__device__ __half g_uT[HID * DIM];
__device__ __half g_h1h[NROI * HID],  g_h1l[NROI * HID];  // reused for h2 split
__device__ __half g_wcT[NHPAD * HID];

// ================= adjacency ==================================================
__global__ void __launch_bounds__(256) adj_kernel(const float* __restrict__ rois) {
    __shared__ float4 sbox[2048];
    __shared__ float4 rbox[16];
    int tid = threadIdx.x;
    int r0 = blockIdx.x * 16;
    if (tid < 16) rbox[tid] = *reinterpret_cast<const float4*>(&rois[(r0 + tid) * 4]);
    const float4* g4 = reinterpret_cast<const float4*>(rois);
    int warp = tid >> 5, lane = tid & 31;
#pragma unroll
    for (int half = 0; half < 2; half++) {
        __syncthreads();
        for (int k = tid; k < 2048; k += 256) sbox[k] = g4[half * 2048 + k];
        __syncthreads();
        for (int t = warp; t < 1024; t += 8) {
            int r = t >> 6, wl = t & 63;
            float4 bi = rbox[r];
            float4 bj = sbox[wl * 32 + lane];
            int i = r0 + r;
            int j = half * 2048 + wl * 32 + lane;
            float iw = fminf(bi.z, bj.z) - fmaxf(bi.x, bj.x) + 1.0f;
            float ih = fminf(bi.w, bj.w) - fmaxf(bi.y, bj.y) + 1.0f;
            unsigned bits = __ballot_sync(0xffffffffu,
                                          iw > 0.0f && ih > 0.0f && j != i);
            if (lane == 0) g_adj[(size_t)i * NW + half * 64 + wl] = bits;
        }
    }
}

// ================= single-kernel connected components =========================
__device__ __forceinline__ void grid_barrier() {
    __syncthreads();
    if (threadIdx.x == 0) {
        __threadfence();
        ULL old = atomicAdd(&g_barc, 1ULL);
        ULL target = (old / CCB + 1) * CCB;
        while (*(volatile ULL*)&g_barc < target) {}
        __threadfence();
    }
    __syncthreads();
}

__global__ void __launch_bounds__(256) cc_kernel(float* __restrict__ out) {
    __shared__ int slj[NROI];
    __shared__ int wmin[NW];
    int tid = threadIdx.x;
    int warp = tid >> 5, lane = tid & 31;
    int gi = blockIdx.x * 256 + tid;
    if (gi < NROI) g_lab[0][gi] = gi;
    if (blockIdx.x == 0 && tid < 33) g_diffs[tid] = 0;
    grid_barrier();

    int src = 0;
    for (int it = 0; it < 32; it++) {
        const int* __restrict__ lp = g_lab[src];
        int* __restrict__ lo = g_lab[src ^ 1];
        for (int k = tid; k < NROI; k += 256) slj[k] = lp[lp[k]];
        __syncthreads();
        if (tid < NW) {
            int m = slj[tid * 32];
#pragma unroll
            for (int b = 1; b < 32; b++) m = min(m, slj[tid * 32 + b]);
            wmin[tid] = m;
        }
        __syncthreads();
        int rbase = blockIdx.x * 32 + warp * 4;
#pragma unroll
        for (int r = 0; r < 4; r++) {
            int i = rbase + r;
            const unsigned* __restrict__ arow = &g_adj[(size_t)i * NW];
            int nb = slj[i];
#pragma unroll
            for (int q = 0; q < 4; q++) {
                int w = lane + q * 32;
                unsigned wb = arow[w];
                if (wb == 0xFFFFFFFFu) {
                    nb = min(nb, wmin[w]);
                } else {
                    while (wb) {
                        int b = __ffs(wb) - 1;
                        wb &= wb - 1;
                        nb = min(nb, slj[w * 32 + b]);
                    }
                }
            }
#pragma unroll
            for (int o = 16; o; o >>= 1)
                nb = min(nb, __shfl_xor_sync(0xffffffffu, nb, o));
            if (lane == 0) {
                lo[i] = nb;
                if (nb != lp[i]) g_diffs[it] = 1;
            }
        }
        grid_barrier();
        src ^= 1;
        if (*(volatile int*)&g_diffs[it] == 0) break;
    }
    if (gi < NROI) {
        int v = g_lab[src][gi];
        out[gi] = (float)g_lab[src][v];
    }
}

// ================= fp32 -> fp16 hi/lo split helpers ==========================
__device__ __forceinline__ void split1h(float x, __half& h, __half& l) {
    h = __float2half_rn(x);
    l = __float2half_rn(x - __half2float(h));
}

// ====== normalize: fused pf hi/lo split AND xn hi/lo split ===================
__global__ void normalize_kernel(const float* __restrict__ pf) {
    __shared__ float red[256];
    int row = blockIdx.x;
    const float4* x = reinterpret_cast<const float4*>(pf + (size_t)row * DIM);
    float4 v = x[threadIdx.x];
    size_t idx = (size_t)row * DIM + threadIdx.x * 4;
    {   // pf split
        __half h0, h1, h2, h3, l0, l1, l2, l3;
        split1h(v.x, h0, l0); split1h(v.y, h1, l1);
        split1h(v.z, h2, l2); split1h(v.w, h3, l3);
        __half2* hp = reinterpret_cast<__half2*>(g_pfh + idx);
        __half2* lp = reinterpret_cast<__half2*>(g_pfl + idx);
        hp[0] = __halves2half2(h0, h1); hp[1] = __halves2half2(h2, h3);
        lp[0] = __halves2half2(l0, l1); lp[1] = __halves2half2(l2, l3);
    }
    float ss = v.x * v.x + v.y * v.y + v.z * v.z + v.w * v.w;
    red[threadIdx.x] = ss;
    __syncthreads();
    for (int s = 128; s > 0; s >>= 1) {
        if (threadIdx.x < s) red[threadIdx.x] += red[threadIdx.x + s];
        __syncthreads();
    }
    float tot = red[0];
    float sc = 1.0f / fmaxf(sqrtf(tot), 1e-6f);
    float4 o = make_float4(v.x * sc, v.y * sc, v.z * sc, v.w * sc);
    *reinterpret_cast<float4*>(g_xn + idx) = o;
    __half h0, h1, h2, h3, l0, l1, l2, l3;
    split1h(o.x, h0, l0); split1h(o.y, h1, l1);
    split1h(o.z, h2, l2); split1h(o.w, h3, l3);
    __half2* hp = reinterpret_cast<__half2*>(g_xnh + idx);
    __half2* lp = reinterpret_cast<__half2*>(g_xnl + idx);
    hp[0] = __halves2half2(h0, h1); hp[1] = __halves2half2(h2, h3);
    lp[0] = __halves2half2(l0, l1); lp[1] = __halves2half2(l2, l3);
    if (threadIdx.x == 0) g_d[row] = (tot * sc) * sc;
}

// X [R][C] fp32 -> single-rounded fp16 T [C][R]
__global__ void __launch_bounds__(256) transpose_single_kernel(
    const float* __restrict__ X, __half* __restrict__ T, int R, int C) {
    __shared__ float t[32][33];
    int bc = blockIdx.x * 32, br = blockIdx.y * 32;
    int tx = threadIdx.x & 31, ty = threadIdx.x >> 5;
#pragma unroll
    for (int k = 0; k < 32; k += 8)
        t[ty + k][tx] = X[(size_t)(br + ty + k) * C + bc + tx];
    __syncthreads();
#pragma unroll
    for (int k = 0; k < 32; k += 8) {
        T[(size_t)(bc + ty + k) * R + br + tx] = __float2half_rn(t[tx][ty + k]);
    }
}

__global__ void __launch_bounds__(256) heads_prep_kernel(
    const float* __restrict__ W_bbox, const float* __restrict__ b_bbox,
    const float* __restrict__ W_cls,  const float* __restrict__ b_cls) {
    int idx = blockIdx.x * 256 + threadIdx.x;
    if (idx >= NHPAD * HID) return;
    int c = idx / HID, k = idx % HID;
    float v = 0.f;
    if (c < NBBX) v = W_bbox[(size_t)k * NBBX + c];
    else if (c < NHEAD) v = W_cls[(size_t)k * NCLS + (c - NBBX)];
    g_wcT[idx] = __float2half_rn(v);
    if (idx < NHPAD) {
        float b = 0.f;
        if (idx < NBBX) b = b_bbox[idx];
        else if (idx < NHEAD) b = b_cls[idx - NBBX];
        g_bc[idx] = b;
    }
}

__global__ void __launch_bounds__(256) heads_route_kernel(float* __restrict__ out) {
    int idx = blockIdx.x * 256 + threadIdx.x;
    if (idx >= NROI * NHEAD) return;
    int m = idx / NHEAD, c = idx % NHEAD;
    size_t o = (size_t)m * NHPAD + c;
    const size_t stride = (size_t)NROI * NHPAD;
    float s = g_upart[o] + g_upart[stride + o] + g_upart[2 * stride + o] +
              g_upart[3 * stride + o] + g_bc[c];
    if (c < NBBX) out[NROI + (size_t)NROI * NCLS + (size_t)m * NBBX + c] = s;
    else          g_logits[(size_t)m * NCLS + (c - NBBX)] = s;
}

// ================= HMMA fp16 2-product GEMM (128x128, 2-stage) ===============
// C = (Ah+Al) @ B^T; Ah/Al fp16 hi/lo, B single fp16; fp32 accumulate.
// EPI 0: store fp32 C (+z offset for split-K)
// EPI 2: store fp32 C AND transposed hi/lo split -> Ch/Cl at [gn*M + gm]
// EPI 3: relu(acc - d[m]*T[m,n] + bias[n]); Ch/Cl row-major split ONLY
#define CTM 128
#define CTN 128
#define CTK 64
#define KPAD 72
#define OFF_AL (128 * KPAD)
#define OFF_B  (2 * 128 * KPAD)
#define BUFE (3 * 128 * KPAD)
#define MM_SMEM (2 * BUFE * 2)          // 110592 bytes

__device__ __forceinline__ uint32_t smem_u32(const void* p) {
    uint32_t a;
    asm("{ .reg .u64 t; cvta.to.shared.u64 t, %1; cvt.u32.u64 %0, t; }"
        : "=r"(a) : "l"(p));
    return a;
}
__device__ __forceinline__ void cpa16(uint32_t s, const void* g) {
    asm volatile("cp.async.ca.shared.global [%0], [%1], 16;" :: "r"(s), "l"(g));
}
#define CP_COMMIT() asm volatile("cp.async.commit_group;" ::: "memory")
#define CP_WAIT1()  asm volatile("cp.async.wait_group 1;" ::: "memory")
#define CP_WAIT0()  asm volatile("cp.async.wait_group 0;" ::: "memory")

#define MMA16816(d, a, b)                                                     \
    asm volatile(                                                             \
        "mma.sync.aligned.m16n8k16.row.col.f32.f16.f16.f32 "                  \
        "{%0,%1,%2,%3}, {%4,%5,%6,%7}, {%8,%9}, {%0,%1,%2,%3};"               \
        : "+f"((d)[0]), "+f"((d)[1]), "+f"((d)[2]), "+f"((d)[3])              \
        : "r"((a)[0]), "r"((a)[1]), "r"((a)[2]), "r"((a)[3]),                 \
          "r"((b)[0]), "r"((b)[1]))

template<int EPI>
__global__ void __launch_bounds__(256) mmagemm_kernel(
    const __half* __restrict__ Ah, const __half* __restrict__ Al,
    const __half* __restrict__ B,
    float* __restrict__ C, int M, int N, int K, int kChunkZ,
    const float* __restrict__ bias, const float* __restrict__ dvec,
    const float* __restrict__ Tm,
    __half* __restrict__ Ch, __half* __restrict__ Cl)
{
    extern __shared__ __align__(16) __half smb[];
    uint32_t sb = smem_u32(smb);
    int tid = threadIdx.x, lane = tid & 31, warp = tid >> 5;
    int wm0 = (warp & 3) * 32, wn0 = (warp >> 2) * 64;
    int m0 = blockIdx.y * CTM, n0 = blockIdx.x * CTN;
    int k0 = blockIdx.z * kChunkZ;
    int nch = kChunkZ / CTK;
    if (gridDim.z > 1) C += (size_t)blockIdx.z * M * N;

    float acc[2][8][4];
#pragma unroll
    for (int i = 0; i < 2; i++)
#pragma unroll
        for (int j = 0; j < 8; j++)
#pragma unroll
            for (int e = 0; e < 4; e++) acc[i][j][e] = 0.f;

    int fr = lane >> 2, fc = (lane & 3) * 2;

    auto ISSUE = [&](int c) {
        int kt = k0 + c * CTK;
        uint32_t base = sb + (uint32_t)(c & 1) * (BUFE * 2);
#pragma unroll
        for (int v = 0; v < 4; v++) {
            int idx = tid + v * 256;
            int row = idx >> 3, cc = (idx & 7) * 8;
            uint32_t soff = (uint32_t)(row * KPAD + cc) * 2;
            size_t ga = (size_t)(m0 + row) * K + kt + cc;
            cpa16(base + soff, Ah + ga);
            cpa16(base + OFF_AL * 2 + soff, Al + ga);
        }
#pragma unroll
        for (int v = 0; v < 2; v++) {
            int idx = tid + v * 256;
            int row = idx >> 2, cc = (idx & 3) * 16;
            uint32_t soff = (uint32_t)(row * KPAD + cc) * 2;
            size_t gb = (size_t)(n0 + row) * K + kt + cc;
            cpa16(base + OFF_B * 2 + soff, B + gb);
            cpa16(base + OFF_B * 2 + soff + 16, B + gb + 8);
        }
        CP_COMMIT();
    };

    ISSUE(0);
    for (int c = 0; c < nch; c++) {
        if (c + 1 < nch) { ISSUE(c + 1); CP_WAIT1(); }
        else             { CP_WAIT0(); }
        __syncthreads();
        const __half* sAh = smb + (c & 1) * BUFE;
        const __half* sAl = sAh + OFF_AL;
        const __half* sB  = smb + (c & 1) * BUFE + OFF_B;
#pragma unroll
        for (int s = 0; s < 4; s++) {
            int kb = s * 16;
            uint32_t ah[2][4], al[2][4], b[8][2];
#pragma unroll
            for (int mt = 0; mt < 2; mt++) {
                int base = (wm0 + mt * 16 + fr) * KPAD + kb + fc;
                ah[mt][0] = *reinterpret_cast<const uint32_t*>(&sAh[base]);
                ah[mt][1] = *reinterpret_cast<const uint32_t*>(&sAh[base + 8 * KPAD]);
                ah[mt][2] = *reinterpret_cast<const uint32_t*>(&sAh[base + 8]);
                ah[mt][3] = *reinterpret_cast<const uint32_t*>(&sAh[base + 8 * KPAD + 8]);
                al[mt][0] = *reinterpret_cast<const uint32_t*>(&sAl[base]);
                al[mt][1] = *reinterpret_cast<const uint32_t*>(&sAl[base + 8 * KPAD]);
                al[mt][2] = *reinterpret_cast<const uint32_t*>(&sAl[base + 8]);
                al[mt][3] = *reinterpret_cast<const uint32_t*>(&sAl[base + 8 * KPAD + 8]);
            }
#pragma unroll
            for (int nt = 0; nt < 8; nt++) {
                int base = (wn0 + nt * 8 + fr) * KPAD + kb + fc;
                b[nt][0] = *reinterpret_cast<const uint32_t*>(&sB[base]);
                b[nt][1] = *reinterpret_cast<const uint32_t*>(&sB[base + 8]);
            }
            // hi sweep then lo sweep (16 independent MMAs each)
#pragma unroll
            for (int mt = 0; mt < 2; mt++)
#pragma unroll
                for (int nt = 0; nt < 8; nt++)
                    MMA16816(acc[mt][nt], ah[mt], b[nt]);
#pragma unroll
            for (int mt = 0; mt < 2; mt++)
#pragma unroll
                for (int nt = 0; nt < 8; nt++)
                    MMA16816(acc[mt][nt], al[mt], b[nt]);
        }
        __syncthreads();
    }

#pragma unroll
    for (int mt = 0; mt < 2; mt++) {
#pragma unroll
        for (int half = 0; half < 2; half++) {
            int gm = m0 + wm0 + mt * 16 + half * 8 + fr;
            float dv = (EPI == 3) ? dvec[gm] : 0.f;
#pragma unroll
            for (int nt = 0; nt < 8; nt++) {
                int gn = n0 + wn0 + nt * 8 + fc;
                float c0 = acc[mt][nt][half * 2 + 0];
                float c1 = acc[mt][nt][half * 2 + 1];
                if (EPI == 3) {
                    float2 t2v = *reinterpret_cast<const float2*>(&Tm[(size_t)gm * N + gn]);
                    float2 b2v = *reinterpret_cast<const float2*>(&bias[gn]);
                    c0 = fmaxf(c0 - dv * t2v.x + b2v.x, 0.f);
                    c1 = fmaxf(c1 - dv * t2v.y + b2v.y, 0.f);
                    __half h0, h1, l0, l1;
                    split1h(c0, h0, l0);
                    split1h(c1, h1, l1);
                    *reinterpret_cast<__half2*>(&Ch[(size_t)gm * N + gn]) =
                        __halves2half2(h0, h1);
                    *reinterpret_cast<__half2*>(&Cl[(size_t)gm * N + gn]) =
                        __halves2half2(l0, l1);
                } else if (EPI == 2) {
                    __half h0, l0, h1, l1;
                    split1h(c0, h0, l0);
                    split1h(c1, h1, l1);
                    Ch[(size_t)gn * M + gm] = h0;
                    Cl[(size_t)gn * M + gm] = l0;
                    Ch[(size_t)(gn + 1) * M + gm] = h1;
                    Cl[(size_t)(gn + 1) * M + gm] = l1;
                }
                if (EPI != 3)
                    *reinterpret_cast<float2*>(&C[(size_t)gm * N + gn]) =
                        make_float2(c0, c1);
            }
        }
    }
}

// reduce split-K partials (4) and write single fp16 (B-side operand)
__global__ void __launch_bounds__(256) reduceK_single_kernel(
    const float* __restrict__ part, __half* __restrict__ o, int total) {
    int i = blockIdx.x * 256 + threadIdx.x;
    if (i >= total) return;
    float s = part[i] + part[total + i] + part[2 * total + i] + part[3 * total + i];
    o[i] = __float2half_rn(s);
}

__global__ void softmax_kernel(float* __restrict__ out) {
    int row = blockIdx.x * 8 + (threadIdx.x >> 5);
    int lane = threadIdx.x & 31;
    if (row >= NROI) return;
    float v = (lane < NCLS) ? g_logits[row * NCLS + lane] : -INFINITY;
    float m = v;
#pragma unroll
    for (int o = 16; o; o >>= 1) m = fmaxf(m, __shfl_xor_sync(0xffffffffu, m, o));
    float e = (lane < NCLS) ? expf(v - m) : 0.f;
    float s = e;
#pragma unroll
    for (int o = 16; o; o >>= 1) s += __shfl_xor_sync(0xffffffffu, s, o);
    if (lane < NCLS) out[NROI + row * NCLS + lane] = e / s;
}

// =============================================================================
extern "C" void kernel_launch(void* const* d_in, const int* in_sizes, int n_in,
                              void* d_out, int out_size) {
    const float* rois   = (const float*)d_in[0];
    const float* pf     = (const float*)d_in[1];
    const float* Wg1    = (const float*)d_in[2];
    const float* bg1    = (const float*)d_in[3];
    const float* Wg2    = (const float*)d_in[4];
    const float* bg2    = (const float*)d_in[5];
    const float* W_bbox = (const float*)d_in[6];
    const float* b_bbox = (const float*)d_in[7];
    const float* W_cls  = (const float*)d_in[8];
    const float* b_cls  = (const float*)d_in[9];
    float* out = (float*)d_out;

    float *xn, *dv, *t1, *upart, *t2;
    cudaGetSymbolAddress((void**)&xn,     g_xn);
    cudaGetSymbolAddress((void**)&dv,     g_d);
    cudaGetSymbolAddress((void**)&t1,     g_t1);
    cudaGetSymbolAddress((void**)&upart,  g_upart);
    cudaGetSymbolAddress((void**)&t2,     g_t2);

    __half *pfh, *pfl, *xnh, *xnl, *xnT, *w1T, *w2T;
    __half *tTh, *tTl, *uT, *h1h, *h1l, *wcT;
    cudaGetSymbolAddress((void**)&pfh, g_pfh);  cudaGetSymbolAddress((void**)&pfl, g_pfl);
    cudaGetSymbolAddress((void**)&xnh, g_xnh);  cudaGetSymbolAddress((void**)&xnl, g_xnl);
    cudaGetSymbolAddress((void**)&xnT, g_xnT);
    cudaGetSymbolAddress((void**)&w1T, g_w1T);
    cudaGetSymbolAddress((void**)&w2T, g_w2T);
    cudaGetSymbolAddress((void**)&tTh, g_tTh);  cudaGetSymbolAddress((void**)&tTl, g_tTl);
    cudaGetSymbolAddress((void**)&uT,  g_uT);
    cudaGetSymbolAddress((void**)&h1h, g_h1h);  cudaGetSymbolAddress((void**)&h1l, g_h1l);
    cudaGetSymbolAddress((void**)&wcT, g_wcT);

    cudaFuncSetAttribute(mmagemm_kernel<0>,
                         cudaFuncAttributeMaxDynamicSharedMemorySize, MM_SMEM);
    cudaFuncSetAttribute(mmagemm_kernel<2>,
                         cudaFuncAttributeMaxDynamicSharedMemorySize, MM_SMEM);
    cudaFuncSetAttribute(mmagemm_kernel<3>,
                         cudaFuncAttributeMaxDynamicSharedMemorySize, MM_SMEM);

    // 1-3: prep; launch #4 = t1 GEMM (profiled slot)
    transpose_single_kernel<<<dim3(HID / 32, DIM / 32), 256>>>(Wg1, w1T, DIM, HID);
    normalize_kernel<<<NROI, 256>>>(pf);      // pf + xn fp16 splits
    adj_kernel<<<NROI / 16, 256>>>(rois);

    // 4 (profiled): t1 = pf @ Wg1; epilogue also writes t1^T fp16 split
    mmagemm_kernel<2><<<dim3(HID / CTN, NROI / CTM, 1), 256, MM_SMEM>>>(
        pfh, pfl, w1T, t1, NROI, HID, DIM, DIM,
        nullptr, nullptr, nullptr, tTh, tTl);

    transpose_single_kernel<<<dim3(DIM / 32, NROI / 32), 256>>>(xn, xnT, NROI, DIM);
    heads_prep_kernel<<<(NHPAD * HID + 255) / 256, 256>>>(W_bbox, b_bbox, W_cls, b_cls);

    // u1^T = t1^T @ xn; split-K x4
    mmagemm_kernel<0><<<dim3(DIM / CTN, HID / CTM, 4), 256, MM_SMEM>>>(
        tTh, tTl, xnT, upart, HID, DIM, NROI, NROI / 4,
        nullptr, nullptr, nullptr, nullptr, nullptr);
    reduceK_single_kernel<<<(HID * DIM + 255) / 256, 256>>>(upart, uT, HID * DIM);

    // h1 = relu(xn @ u1 - d*t1 + bg1); split-only epilogue -> h1h/h1l
    mmagemm_kernel<3><<<dim3(HID / CTN, NROI / CTM, 1), 256, MM_SMEM>>>(
        xnh, xnl, uT, nullptr, NROI, HID, DIM, DIM, bg1, dv, t1, h1h, h1l);

    transpose_single_kernel<<<dim3(HID / 32, HID / 32), 256>>>(Wg2, w2T, HID, HID);

    // t2 = h1 @ Wg2; epilogue writes t2^T fp16 split
    mmagemm_kernel<2><<<dim3(HID / CTN, NROI / CTM, 1), 256, MM_SMEM>>>(
        h1h, h1l, w2T, t2, NROI, HID, HID, HID,
        nullptr, nullptr, nullptr, tTh, tTl);

    // u2^T = t2^T @ xn; split-K x4
    mmagemm_kernel<0><<<dim3(DIM / CTN, HID / CTM, 4), 256, MM_SMEM>>>(
        tTh, tTl, xnT, upart, HID, DIM, NROI, NROI / 4,
        nullptr, nullptr, nullptr, nullptr, nullptr);
    reduceK_single_kernel<<<(HID * DIM + 255) / 256, 256>>>(upart, uT, HID * DIM);

    // h2 = relu(xn @ u2 - d*t2 + bg2); split-only epilogue into h1h/h1l (reuse)
    mmagemm_kernel<3><<<dim3(HID / CTN, NROI / CTM, 1), 256, MM_SMEM>>>(
        xnh, xnl, uT, nullptr, NROI, HID, DIM, DIM, bg2, dv, t2, h1h, h1l);

    // heads: [bbox|cls] = h2 @ Wc  (M=4096, N=128, K=512), split-K x4
    mmagemm_kernel<0><<<dim3(1, NROI / CTM, 4), 256, MM_SMEM>>>(
        h1h, h1l, wcT, upart, NROI, NHPAD, HID, HID / 4,
        nullptr, nullptr, nullptr, nullptr, nullptr);
    heads_route_kernel<<<(NROI * NHEAD + 255) / 256, 256>>>(out);
    softmax_kernel<<<NROI / 8, 256>>>(out);

    // connected components (single persistent kernel)
    cc_kernel<<<CCB, 256>>>(out);
}

// round 17
// speedup vs baseline: 1.2850x; 1.2850x over previous
#include <cuda_runtime.h>
#include <cuda_bf16.h>
#include <math.h>
#include <stdint.h>

#define NROI 4096
#define DIM  1024
#define HID  512
#define NCLS 21
#define NBBX 84
#define NHEAD 105         // 84 + 21
#define NHPAD 128
#define NW   128
#define CCB  128

typedef unsigned long long ULL;

// ================= scratch (static device globals) ===========================
__device__ float    g_xn[NROI * DIM];
__device__ float    g_d[NROI];
__device__ float    g_t1[NROI * HID];
__device__ float    g_upart[4 * DIM * HID];
__device__ float    g_t2[NROI * HID];
__device__ unsigned g_adj[NROI * NW];
__device__ int      g_lab[2][NROI];
__device__ int      g_diffs[33];
__device__ ULL      g_barc;
__device__ float    g_bc[NHPAD];
__device__ __nv_bfloat16 g_pfh[NROI * DIM],  g_pfl[NROI * DIM];
__device__ __nv_bfloat16 g_xnh[NROI * DIM],  g_xnl[NROI * DIM];
__device__ __nv_bfloat16 g_xnTh[DIM * NROI], g_xnTl[DIM * NROI];
__device__ __nv_bfloat16 g_w1Th[HID * DIM],  g_w1Tl[HID * DIM];
__device__ __nv_bfloat16 g_w2Th[HID * HID],  g_w2Tl[HID * HID];
__device__ __nv_bfloat16 g_tTh[HID * NROI],  g_tTl[HID * NROI];
__device__ __nv_bfloat16 g_uTh[HID * DIM],   g_uTl[HID * DIM];
__device__ __nv_bfloat16 g_h1h[NROI * HID],  g_h1l[NROI * HID];  // reused for h2 split
__device__ __nv_bfloat16 g_wcTh[NHPAD * HID], g_wcTl[NHPAD * HID];

// ================= adjacency ==================================================
__global__ void __launch_bounds__(256) adj_kernel(const float* __restrict__ rois) {
    __shared__ float4 sbox[2048];
    __shared__ float4 rbox[16];
    int tid = threadIdx.x;
    int r0 = blockIdx.x * 16;
    if (tid < 16) rbox[tid] = *reinterpret_cast<const float4*>(&rois[(r0 + tid) * 4]);
    const float4* g4 = reinterpret_cast<const float4*>(rois);
    int warp = tid >> 5, lane = tid & 31;
#pragma unroll
    for (int half = 0; half < 2; half++) {
        __syncthreads();
        for (int k = tid; k < 2048; k += 256) sbox[k] = g4[half * 2048 + k];
        __syncthreads();
        for (int t = warp; t < 1024; t += 8) {
            int r = t >> 6, wl = t & 63;
            float4 bi = rbox[r];
            float4 bj = sbox[wl * 32 + lane];
            int i = r0 + r;
            int j = half * 2048 + wl * 32 + lane;
            float iw = fminf(bi.z, bj.z) - fmaxf(bi.x, bj.x) + 1.0f;
            float ih = fminf(bi.w, bj.w) - fmaxf(bi.y, bj.y) + 1.0f;
            unsigned bits = __ballot_sync(0xffffffffu,
                                          iw > 0.0f && ih > 0.0f && j != i);
            if (lane == 0) g_adj[(size_t)i * NW + half * 64 + wl] = bits;
        }
    }
}

// ================= single-kernel connected components =========================
__device__ __forceinline__ void grid_barrier() {
    __syncthreads();
    if (threadIdx.x == 0) {
        __threadfence();
        ULL old = atomicAdd(&g_barc, 1ULL);
        ULL target = (old / CCB + 1) * CCB;
        while (*(volatile ULL*)&g_barc < target) {}
        __threadfence();
    }
    __syncthreads();
}

__global__ void __launch_bounds__(256) cc_kernel(float* __restrict__ out) {
    __shared__ int slj[NROI];
    __shared__ int wmin[NW];
    int tid = threadIdx.x;
    int warp = tid >> 5, lane = tid & 31;
    int gi = blockIdx.x * 256 + tid;
    if (gi < NROI) g_lab[0][gi] = gi;
    if (blockIdx.x == 0 && tid < 33) g_diffs[tid] = 0;
    grid_barrier();

    int src = 0;
    for (int it = 0; it < 32; it++) {
        const int* __restrict__ lp = g_lab[src];
        int* __restrict__ lo = g_lab[src ^ 1];
        for (int k = tid; k < NROI; k += 256) slj[k] = lp[lp[k]];
        __syncthreads();
        if (tid < NW) {
            int m = slj[tid * 32];
#pragma unroll
            for (int b = 1; b < 32; b++) m = min(m, slj[tid * 32 + b]);
            wmin[tid] = m;
        }
        __syncthreads();
        int rbase = blockIdx.x * 32 + warp * 4;
#pragma unroll
        for (int r = 0; r < 4; r++) {
            int i = rbase + r;
            const unsigned* __restrict__ arow = &g_adj[(size_t)i * NW];
            int nb = slj[i];
#pragma unroll
            for (int q = 0; q < 4; q++) {
                int w = lane + q * 32;
                unsigned wb = arow[w];
                if (wb == 0xFFFFFFFFu) {
                    nb = min(nb, wmin[w]);
                } else {
                    while (wb) {
                        int b = __ffs(wb) - 1;
                        wb &= wb - 1;
                        nb = min(nb, slj[w * 32 + b]);
                    }
                }
            }
#pragma unroll
            for (int o = 16; o; o >>= 1)
                nb = min(nb, __shfl_xor_sync(0xffffffffu, nb, o));
            if (lane == 0) {
                lo[i] = nb;
                if (nb != lp[i]) g_diffs[it] = 1;
            }
        }
        grid_barrier();
        src ^= 1;
        if (*(volatile int*)&g_diffs[it] == 0) break;
    }
    if (gi < NROI) {
        int v = g_lab[src][gi];
        out[gi] = (float)g_lab[src][v];
    }
}

// ================= fp32 -> bf16 hi/lo split helpers ==========================
__device__ __forceinline__ void split1(float x, __nv_bfloat16& h, __nv_bfloat16& l) {
    h = __float2bfloat16_rn(x);
    l = __float2bfloat16_rn(x - __bfloat162float(h));
}

// ====== normalize: fused pf hi/lo split AND xn hi/lo split ===================
__global__ void normalize_kernel(const float* __restrict__ pf) {
    __shared__ float red[256];
    int row = blockIdx.x;
    const float4* x = reinterpret_cast<const float4*>(pf + (size_t)row * DIM);
    float4 v = x[threadIdx.x];
    size_t idx = (size_t)row * DIM + threadIdx.x * 4;
    {   // pf split (values unchanged from dataset)
        __nv_bfloat16 h0, h1, h2, h3, l0, l1, l2, l3;
        split1(v.x, h0, l0); split1(v.y, h1, l1);
        split1(v.z, h2, l2); split1(v.w, h3, l3);
        __nv_bfloat162* hp = reinterpret_cast<__nv_bfloat162*>(g_pfh + idx);
        __nv_bfloat162* lp = reinterpret_cast<__nv_bfloat162*>(g_pfl + idx);
        hp[0] = __nv_bfloat162(h0, h1); hp[1] = __nv_bfloat162(h2, h3);
        lp[0] = __nv_bfloat162(l0, l1); lp[1] = __nv_bfloat162(l2, l3);
    }
    float ss = v.x * v.x + v.y * v.y + v.z * v.z + v.w * v.w;
    red[threadIdx.x] = ss;
    __syncthreads();
    for (int s = 128; s > 0; s >>= 1) {
        if (threadIdx.x < s) red[threadIdx.x] += red[threadIdx.x + s];
        __syncthreads();
    }
    float tot = red[0];
    float sc = 1.0f / fmaxf(sqrtf(tot), 1e-6f);
    float4 o = make_float4(v.x * sc, v.y * sc, v.z * sc, v.w * sc);
    *reinterpret_cast<float4*>(g_xn + idx) = o;
    __nv_bfloat16 h0, h1, h2, h3, l0, l1, l2, l3;
    split1(o.x, h0, l0); split1(o.y, h1, l1);
    split1(o.z, h2, l2); split1(o.w, h3, l3);
    __nv_bfloat162* hp = reinterpret_cast<__nv_bfloat162*>(g_xnh + idx);
    __nv_bfloat162* lp = reinterpret_cast<__nv_bfloat162*>(g_xnl + idx);
    hp[0] = __nv_bfloat162(h0, h1); hp[1] = __nv_bfloat162(h2, h3);
    lp[0] = __nv_bfloat162(l0, l1); lp[1] = __nv_bfloat162(l2, l3);
    if (threadIdx.x == 0) g_d[row] = (tot * sc) * sc;
}

__global__ void __launch_bounds__(256) split_transpose_kernel(
    const float* __restrict__ X, __nv_bfloat16* __restrict__ hiT,
    __nv_bfloat16* __restrict__ loT, int R, int C) {
    __shared__ float t[32][33];
    int bc = blockIdx.x * 32, br = blockIdx.y * 32;
    int tx = threadIdx.x & 31, ty = threadIdx.x >> 5;
#pragma unroll
    for (int k = 0; k < 32; k += 8)
        t[ty + k][tx] = X[(size_t)(br + ty + k) * C + bc + tx];
    __syncthreads();
#pragma unroll
    for (int k = 0; k < 32; k += 8) {
        float v = t[tx][ty + k];
        __nv_bfloat16 h, l;
        split1(v, h, l);
        size_t o = (size_t)(bc + ty + k) * R + br + tx;
        hiT[o] = h;
        loT[o] = l;
    }
}

__global__ void __launch_bounds__(256) heads_prep_kernel(
    const float* __restrict__ W_bbox, const float* __restrict__ b_bbox,
    const float* __restrict__ W_cls,  const float* __restrict__ b_cls) {
    int idx = blockIdx.x * 256 + threadIdx.x;
    if (idx >= NHPAD * HID) return;
    int c = idx / HID, k = idx % HID;
    float v = 0.f;
    if (c < NBBX) v = W_bbox[(size_t)k * NBBX + c];
    else if (c < NHEAD) v = W_cls[(size_t)k * NCLS + (c - NBBX)];
    __nv_bfloat16 h, l;
    split1(v, h, l);
    g_wcTh[idx] = h;
    g_wcTl[idx] = l;
    if (idx < NHPAD) {
        float b = 0.f;
        if (idx < NBBX) b = b_bbox[idx];
        else if (idx < NHEAD) b = b_cls[idx - NBBX];
        g_bc[idx] = b;
    }
}

// ===== fused heads epilogue: reduce 4 partials + bias, write bbox, softmax ===
// one warp per ROI row
__global__ void __launch_bounds__(256) heads_final_kernel(float* __restrict__ out) {
    int m = blockIdx.x * 8 + (threadIdx.x >> 5);
    int lane = threadIdx.x & 31;
    const size_t stride = (size_t)NROI * NHPAD;
    const float* p = g_upart + (size_t)m * NHPAD;

    // bbox: c = lane, lane+32, lane+64 (lanes 0..19 only for the third)
    float* bb = out + NROI + (size_t)NROI * NCLS + (size_t)m * NBBX;
#pragma unroll
    for (int q = 0; q < 3; q++) {
        int c = lane + q * 32;
        if (c < NBBX) {
            float s = p[c] + p[stride + c] + p[2 * stride + c] +
                      p[3 * stride + c] + g_bc[c];
            bb[c] = s;
        }
    }
    // cls logits: c = 84 + lane (lanes 0..20)
    float v = -INFINITY;
    if (lane < NCLS) {
        int c = NBBX + lane;
        v = p[c] + p[stride + c] + p[2 * stride + c] + p[3 * stride + c] + g_bc[c];
    }
    float mx = v;
#pragma unroll
    for (int o = 16; o; o >>= 1) mx = fmaxf(mx, __shfl_xor_sync(0xffffffffu, mx, o));
    float e = (lane < NCLS) ? expf(v - mx) : 0.f;
    float s = e;
#pragma unroll
    for (int o = 16; o; o >>= 1) s += __shfl_xor_sync(0xffffffffu, s, o);
    if (lane < NCLS) out[NROI + (size_t)m * NCLS + lane] = e / s;
}

// ================= HMMA bf16-split GEMM (R12/R15 config) =====================
// EPI 0: store fp32 C (+z offset for split-K)
// EPI 2: store fp32 C AND transposed hi/lo split -> Ch/Cl at [gn*M + gm]
// EPI 3: relu(acc - d[m]*T[m,n] + bias[n]); Ch/Cl row-major split ONLY
#define CTM 128
#define CTN 128
#define CTK 64
#define KPAD 72
#define BUFE (4 * 128 * KPAD)
#define MM_SMEM (2 * BUFE * 2)

__device__ __forceinline__ uint32_t smem_u32(const void* p) {
    uint32_t a;
    asm("{ .reg .u64 t; cvta.to.shared.u64 t, %1; cvt.u32.u64 %0, t; }"
        : "=r"(a) : "l"(p));
    return a;
}
__device__ __forceinline__ void cpa16(uint32_t s, const void* g) {
    asm volatile("cp.async.ca.shared.global [%0], [%1], 16;" :: "r"(s), "l"(g));
}
#define CP_COMMIT() asm volatile("cp.async.commit_group;" ::: "memory")
#define CP_WAIT1()  asm volatile("cp.async.wait_group 1;" ::: "memory")
#define CP_WAIT0()  asm volatile("cp.async.wait_group 0;" ::: "memory")

#define MMA16816(d, a, b)                                                     \
    asm volatile(                                                             \
        "mma.sync.aligned.m16n8k16.row.col.f32.bf16.bf16.f32 "                \
        "{%0,%1,%2,%3}, {%4,%5,%6,%7}, {%8,%9}, {%0,%1,%2,%3};"               \
        : "+f"((d)[0]), "+f"((d)[1]), "+f"((d)[2]), "+f"((d)[3])              \
        : "r"((a)[0]), "r"((a)[1]), "r"((a)[2]), "r"((a)[3]),                 \
          "r"((b)[0]), "r"((b)[1]))

template<int EPI>
__global__ void __launch_bounds__(256) mmagemm_kernel(
    const __nv_bfloat16* __restrict__ Ah, const __nv_bfloat16* __restrict__ Al,
    const __nv_bfloat16* __restrict__ Bh, const __nv_bfloat16* __restrict__ Bl,
    float* __restrict__ C, int M, int N, int K, int kChunkZ,
    const float* __restrict__ bias, const float* __restrict__ dvec,
    const float* __restrict__ Tm,
    __nv_bfloat16* __restrict__ Ch, __nv_bfloat16* __restrict__ Cl)
{
    extern __shared__ __align__(16) __nv_bfloat16 smb[];
    uint32_t sb = smem_u32(smb);
    int tid = threadIdx.x, lane = tid & 31, warp = tid >> 5;
    int wm0 = (warp & 3) * 32, wn0 = (warp >> 2) * 64;
    int m0 = blockIdx.y * CTM, n0 = blockIdx.x * CTN;
    int k0 = blockIdx.z * kChunkZ;
    int nch = kChunkZ / CTK;
    if (gridDim.z > 1) C += (size_t)blockIdx.z * M * N;

    float acc[2][8][4];
#pragma unroll
    for (int i = 0; i < 2; i++)
#pragma unroll
        for (int j = 0; j < 8; j++)
#pragma unroll
            for (int e = 0; e < 4; e++) acc[i][j][e] = 0.f;

    int fr = lane >> 2, fc = (lane & 3) * 2;

    auto ISSUE = [&](int c) {
        int kt = k0 + c * CTK;
        uint32_t base = sb + (uint32_t)(c & 1) * (BUFE * 2);
#pragma unroll
        for (int v = 0; v < 4; v++) {
            int idx = tid + v * 256;
            int row = idx >> 3, cc = (idx & 7) * 8;
            uint32_t soff = (uint32_t)(row * KPAD + cc) * 2;
            size_t ga = (size_t)(m0 + row) * K + kt + cc;
            size_t gb = (size_t)(n0 + row) * K + kt + cc;
            cpa16(base + soff, Ah + ga);
            cpa16(base + 128 * KPAD * 2 + soff, Al + ga);
            cpa16(base + 2 * 128 * KPAD * 2 + soff, Bh + gb);
            cpa16(base + 3 * 128 * KPAD * 2 + soff, Bl + gb);
        }
        CP_COMMIT();
    };

    ISSUE(0);
    for (int c = 0; c < nch; c++) {
        if (c + 1 < nch) { ISSUE(c + 1); CP_WAIT1(); }
        else             { CP_WAIT0(); }
        __syncthreads();
        const __nv_bfloat16* sAh = smb + (c & 1) * BUFE;
        const __nv_bfloat16* sAl = sAh + 128 * KPAD;
        const __nv_bfloat16* sBh = sAl + 128 * KPAD;
        const __nv_bfloat16* sBl = sBh + 128 * KPAD;
#pragma unroll
        for (int s = 0; s < 4; s++) {
            int kb = s * 16;
            uint32_t ah[2][4], al[2][4], bh[8][2], bl[8][2];
#pragma unroll
            for (int mt = 0; mt < 2; mt++) {
                int base = (wm0 + mt * 16 + fr) * KPAD + kb + fc;
                ah[mt][0] = *reinterpret_cast<const uint32_t*>(&sAh[base]);
                ah[mt][1] = *reinterpret_cast<const uint32_t*>(&sAh[base + 8 * KPAD]);
                ah[mt][2] = *reinterpret_cast<const uint32_t*>(&sAh[base + 8]);
                ah[mt][3] = *reinterpret_cast<const uint32_t*>(&sAh[base + 8 * KPAD + 8]);
                al[mt][0] = *reinterpret_cast<const uint32_t*>(&sAl[base]);
                al[mt][1] = *reinterpret_cast<const uint32_t*>(&sAl[base + 8 * KPAD]);
                al[mt][2] = *reinterpret_cast<const uint32_t*>(&sAl[base + 8]);
                al[mt][3] = *reinterpret_cast<const uint32_t*>(&sAl[base + 8 * KPAD + 8]);
            }
#pragma unroll
            for (int nt = 0; nt < 8; nt++) {
                int base = (wn0 + nt * 8 + fr) * KPAD + kb + fc;
                bh[nt][0] = *reinterpret_cast<const uint32_t*>(&sBh[base]);
                bh[nt][1] = *reinterpret_cast<const uint32_t*>(&sBh[base + 8]);
                bl[nt][0] = *reinterpret_cast<const uint32_t*>(&sBl[base]);
                bl[nt][1] = *reinterpret_cast<const uint32_t*>(&sBl[base + 8]);
            }
            // hh, hl, lh sweeps; per-acc order unchanged (bit-identical)
#pragma unroll
            for (int mt = 0; mt < 2; mt++)
#pragma unroll
                for (int nt = 0; nt < 8; nt++)
                    MMA16816(acc[mt][nt], ah[mt], bh[nt]);
#pragma unroll
            for (int mt = 0; mt < 2; mt++)
#pragma unroll
                for (int nt = 0; nt < 8; nt++)
                    MMA16816(acc[mt][nt], ah[mt], bl[nt]);
#pragma unroll
            for (int mt = 0; mt < 2; mt++)
#pragma unroll
                for (int nt = 0; nt < 8; nt++)
                    MMA16816(acc[mt][nt], al[mt], bh[nt]);
        }
        __syncthreads();
    }

#pragma unroll
    for (int mt = 0; mt < 2; mt++) {
#pragma unroll
        for (int half = 0; half < 2; half++) {
            int gm = m0 + wm0 + mt * 16 + half * 8 + fr;
            float dv = (EPI == 3) ? dvec[gm] : 0.f;
#pragma unroll
            for (int nt = 0; nt < 8; nt++) {
                int gn = n0 + wn0 + nt * 8 + fc;
                float c0 = acc[mt][nt][half * 2 + 0];
                float c1 = acc[mt][nt][half * 2 + 1];
                if (EPI == 3) {
                    float2 t2v = *reinterpret_cast<const float2*>(&Tm[(size_t)gm * N + gn]);
                    float2 b2v = *reinterpret_cast<const float2*>(&bias[gn]);
                    c0 = fmaxf(c0 - dv * t2v.x + b2v.x, 0.f);
                    c1 = fmaxf(c1 - dv * t2v.y + b2v.y, 0.f);
                    __nv_bfloat16 h0, h1, l0, l1;
                    split1(c0, h0, l0);
                    split1(c1, h1, l1);
                    *reinterpret_cast<__nv_bfloat162*>(&Ch[(size_t)gm * N + gn]) =
                        __nv_bfloat162(h0, h1);
                    *reinterpret_cast<__nv_bfloat162*>(&Cl[(size_t)gm * N + gn]) =
                        __nv_bfloat162(l0, l1);
                } else if (EPI == 2) {
                    __nv_bfloat16 h0, l0, h1, l1;
                    split1(c0, h0, l0);
                    split1(c1, h1, l1);
                    Ch[(size_t)gn * M + gm] = h0;
                    Cl[(size_t)gn * M + gm] = l0;
                    Ch[(size_t)(gn + 1) * M + gm] = h1;
                    Cl[(size_t)(gn + 1) * M + gm] = l1;
                }
                if (EPI != 3)
                    *reinterpret_cast<float2*>(&C[(size_t)gm * N + gn]) =
                        make_float2(c0, c1);
            }
        }
    }
}

// reduce split-K partials (4) and write bf16 hi/lo
__global__ void __launch_bounds__(256) reduceK_split_kernel(
    const float* __restrict__ part, __nv_bfloat16* __restrict__ oh,
    __nv_bfloat16* __restrict__ ol, int total) {
    int i = blockIdx.x * 256 + threadIdx.x;
    if (i >= total) return;
    float s = part[i] + part[total + i] + part[2 * total + i] + part[3 * total + i];
    __nv_bfloat16 h, l;
    split1(s, h, l);
    oh[i] = h;
    ol[i] = l;
}

// =============================================================================
extern "C" void kernel_launch(void* const* d_in, const int* in_sizes, int n_in,
                              void* d_out, int out_size) {
    const float* rois   = (const float*)d_in[0];
    const float* pf     = (const float*)d_in[1];
    const float* Wg1    = (const float*)d_in[2];
    const float* bg1    = (const float*)d_in[3];
    const float* Wg2    = (const float*)d_in[4];
    const float* bg2    = (const float*)d_in[5];
    const float* W_bbox = (const float*)d_in[6];
    const float* b_bbox = (const float*)d_in[7];
    const float* W_cls  = (const float*)d_in[8];
    const float* b_cls  = (const float*)d_in[9];
    float* out = (float*)d_out;

    float *xn, *dv, *t1, *upart, *t2;
    cudaGetSymbolAddress((void**)&xn,     g_xn);
    cudaGetSymbolAddress((void**)&dv,     g_d);
    cudaGetSymbolAddress((void**)&t1,     g_t1);
    cudaGetSymbolAddress((void**)&upart,  g_upart);
    cudaGetSymbolAddress((void**)&t2,     g_t2);

    __nv_bfloat16 *pfh, *pfl, *xnh, *xnl, *xnTh, *xnTl, *w1Th, *w1Tl;
    __nv_bfloat16 *w2Th, *w2Tl, *tTh, *tTl, *uTh, *uTl, *h1h, *h1l;
    __nv_bfloat16 *wcTh, *wcTl;
    cudaGetSymbolAddress((void**)&pfh,  g_pfh);  cudaGetSymbolAddress((void**)&pfl,  g_pfl);
    cudaGetSymbolAddress((void**)&xnh,  g_xnh);  cudaGetSymbolAddress((void**)&xnl,  g_xnl);
    cudaGetSymbolAddress((void**)&xnTh, g_xnTh); cudaGetSymbolAddress((void**)&xnTl, g_xnTl);
    cudaGetSymbolAddress((void**)&w1Th, g_w1Th); cudaGetSymbolAddress((void**)&w1Tl, g_w1Tl);
    cudaGetSymbolAddress((void**)&w2Th, g_w2Th); cudaGetSymbolAddress((void**)&w2Tl, g_w2Tl);
    cudaGetSymbolAddress((void**)&tTh,  g_tTh);  cudaGetSymbolAddress((void**)&tTl,  g_tTl);
    cudaGetSymbolAddress((void**)&uTh,  g_uTh);  cudaGetSymbolAddress((void**)&uTl,  g_uTl);
    cudaGetSymbolAddress((void**)&h1h,  g_h1h);  cudaGetSymbolAddress((void**)&h1l,  g_h1l);
    cudaGetSymbolAddress((void**)&wcTh, g_wcTh); cudaGetSymbolAddress((void**)&wcTl, g_wcTl);

    cudaFuncSetAttribute(mmagemm_kernel<0>,
                         cudaFuncAttributeMaxDynamicSharedMemorySize, MM_SMEM);
    cudaFuncSetAttribute(mmagemm_kernel<2>,
                         cudaFuncAttributeMaxDynamicSharedMemorySize, MM_SMEM);
    cudaFuncSetAttribute(mmagemm_kernel<3>,
                         cudaFuncAttributeMaxDynamicSharedMemorySize, MM_SMEM);

    // 1-3: prep; launch #4 = t1 GEMM (profiled slot)
    split_transpose_kernel<<<dim3(HID / 32, DIM / 32), 256>>>(Wg1, w1Th, w1Tl, DIM, HID);
    normalize_kernel<<<NROI, 256>>>(pf);      // also writes pf + xn bf16 splits
    adj_kernel<<<NROI / 16, 256>>>(rois);

    // 4 (profiled): t1 = pf @ Wg1; epilogue also writes t1^T bf16 split
    mmagemm_kernel<2><<<dim3(HID / CTN, NROI / CTM, 1), 256, MM_SMEM>>>(
        pfh, pfl, w1Th, w1Tl, t1, NROI, HID, DIM, DIM,
        nullptr, nullptr, nullptr, tTh, tTl);

    split_transpose_kernel<<<dim3(DIM / 32, NROI / 32), 256>>>(xn, xnTh, xnTl, NROI, DIM);
    heads_prep_kernel<<<(NHPAD * HID + 255) / 256, 256>>>(W_bbox, b_bbox, W_cls, b_cls);

    // u1^T = t1^T @ xn; split-K x4
    mmagemm_kernel<0><<<dim3(DIM / CTN, HID / CTM, 4), 256, MM_SMEM>>>(
        tTh, tTl, xnTh, xnTl, upart, HID, DIM, NROI, NROI / 4,
        nullptr, nullptr, nullptr, nullptr, nullptr);
    reduceK_split_kernel<<<(HID * DIM + 255) / 256, 256>>>(upart, uTh, uTl, HID * DIM);

    // h1 = relu(xn @ u1 - d*t1 + bg1); split-only epilogue -> h1h/h1l
    mmagemm_kernel<3><<<dim3(HID / CTN, NROI / CTM, 1), 256, MM_SMEM>>>(
        xnh, xnl, uTh, uTl, nullptr, NROI, HID, DIM, DIM, bg1, dv, t1, h1h, h1l);

    split_transpose_kernel<<<dim3(HID / 32, HID / 32), 256>>>(Wg2, w2Th, w2Tl, HID, HID);

    // t2 = h1 @ Wg2; epilogue writes t2^T bf16 split
    mmagemm_kernel<2><<<dim3(HID / CTN, NROI / CTM, 1), 256, MM_SMEM>>>(
        h1h, h1l, w2Th, w2Tl, t2, NROI, HID, HID, HID,
        nullptr, nullptr, nullptr, tTh, tTl);

    // u2^T = t2^T @ xn; split-K x4
    mmagemm_kernel<0><<<dim3(DIM / CTN, HID / CTM, 4), 256, MM_SMEM>>>(
        tTh, tTl, xnTh, xnTl, upart, HID, DIM, NROI, NROI / 4,
        nullptr, nullptr, nullptr, nullptr, nullptr);
    reduceK_split_kernel<<<(HID * DIM + 255) / 256, 256>>>(upart, uTh, uTl, HID * DIM);

    // h2 = relu(xn @ u2 - d*t2 + bg2); split-only epilogue into h1h/h1l (reuse)
    mmagemm_kernel<3><<<dim3(HID / CTN, NROI / CTM, 1), 256, MM_SMEM>>>(
        xnh, xnl, uTh, uTl, nullptr, NROI, HID, DIM, DIM, bg2, dv, t2, h1h, h1l);

    // heads: [bbox|cls] = h2 @ Wc  (M=4096, N=128, K=512), split-K x4
    mmagemm_kernel<0><<<dim3(1, NROI / CTM, 4), 256, MM_SMEM>>>(
        h1h, h1l, wcTh, wcTl, upart, NROI, NHPAD, HID, HID / 4,
        nullptr, nullptr, nullptr, nullptr, nullptr);
    // fused reduce + bias + bbox store + softmax (one warp per row)
    heads_final_kernel<<<NROI / 8, 256>>>(out);

    // connected components (single persistent kernel)
    cc_kernel<<<CCB, 256>>>(out);
}